// round 8
// baseline (speedup 1.0000x reference)
#include <cuda_runtime.h>
#include <math.h>

#define Bn 65536
#define NP 2080  // 64*65/2 pairs i<=j

// ---------- device scratch ----------
__device__ float g_cosd[64], g_Finv[4096], g_metric[4096], g_Wf[4096], g_bf[64];
__device__ float g_Dsym[NP * 64];
__device__ unsigned char g_pi[NP], g_pj[NP];
__device__ float g_WqT[4096], g_WkT[4096], g_WvT[4096], g_WoT[4096], g_WuT[4096], g_WsT[4096];
__device__ double g_aug[64 * 128];
__device__ float g_topo[64 * Bn], g_qv[64 * Bn], g_kv[64 * Bn], g_vv[64 * Bn];
__device__ float g_quant[64 * Bn], g_uv[64 * Bn], g_cand[64 * Bn], g_xm[64 * Bn];

// ---------- packed f32x2 ----------
typedef unsigned long long u64;
__device__ __forceinline__ u64 pk2(float lo, float hi) {
    u64 r; asm("mov.b64 %0, {%1, %2};" : "=l"(r) : "f"(lo), "f"(hi)); return r;
}
__device__ __forceinline__ void upk2(u64 v, float& lo, float& hi) {
    asm("mov.b64 {%0, %1}, %2;" : "=f"(lo), "=f"(hi) : "l"(v));
}
__device__ __forceinline__ u64 ffma2(u64 a, u64 b, u64 c) {
    u64 d; asm("fma.rn.f32x2 %0, %1, %2, %3;" : "=l"(d) : "l"(a), "l"(b), "l"(c)); return d;
}
// acc[o/2] += in_sh[i*256+tid] * W_sh[i*64+o]
__device__ __forceinline__ void gemv64(const float* in_sh, const float* W_sh, int tid, u64 acc[32]) {
#pragma unroll 4
    for (int i = 0; i < 64; i++) {
        float x = in_sh[i * 256 + tid];
        u64 xv = pk2(x, x);
        const ulonglong2* row = (const ulonglong2*)(W_sh + i * 64);
#pragma unroll
        for (int q = 0; q < 16; q++) {
            ulonglong2 w = row[q];
            acc[2 * q] = ffma2(xv, w.x, acc[2 * q]);
            acc[2 * q + 1] = ffma2(xv, w.y, acc[2 * q + 1]);
        }
    }
}

// ============ K0a: single-CTA precompute ============
__global__ void k0a(const float* __restrict__ phase, const float* __restrict__ q_w,
                    const float* __restrict__ k_w, const float* __restrict__ v_w,
                    const float* __restrict__ o_w, const float* __restrict__ update_w,
                    const float* __restrict__ state_w, const float* __restrict__ fisher_m,
                    const float* __restrict__ metric_m, const float* __restrict__ proj_w,
                    const float* __restrict__ proj_b, const float* __restrict__ obj_emb,
                    const float* __restrict__ morphisms, const float* __restrict__ functor_w,
                    const float* __restrict__ out_w, const float* __restrict__ out_b) {
    __shared__ float s_a[4096], s_b[4096], s_fw[64];
    __shared__ double s_f[64], s_bv[2], s_pv;
    __shared__ int s_br[2], s_piv;
    int tid = threadIdx.x;
    if (tid < 64) g_cosd[tid] = cosf(phase[tid >> 3] - phase[tid & 7]);
    for (int idx = tid; idx < 4096; idx += 256) {
        int o = idx >> 6, i = idx & 63;
        g_WqT[i * 64 + o] = q_w[idx];  g_WkT[i * 64 + o] = k_w[idx];
        g_WvT[i * 64 + o] = v_w[idx];  g_WoT[i * 64 + o] = o_w[idx];
        g_WuT[i * 64 + o] = update_w[o * 128 + i];  // h0=0: only first half
        g_WsT[i * 64 + o] = state_w[o * 128 + i];
    }
    for (int idx = tid; idx < 4096; idx += 256) {
        int i = idx >> 6, j = idx & 63;
        float sf = 0.f, sm = 0.f;
        for (int k = 0; k < 64; k++) {
            sf += fisher_m[i * 64 + k] * fisher_m[j * 64 + k];
            sm += metric_m[i * 64 + k] * metric_m[j * 64 + k];
        }
        g_metric[idx] = sm;
        int c = j;
        g_aug[i * 128 + c] = (double)sf;
        g_aug[i * 128 + 64 + c] = (c == i) ? 1.0 : 0.0;
    }
    if (tid == 0) {
        int p = 0;
        for (int i = 0; i < 64; i++)
            for (int j = i; j < 64; j++) { g_pi[p] = i; g_pj[p] = j; p++; }
    }
    __syncthreads();
    // Gauss-Jordan (fp64, partial pivot) -> Finv
    for (int col = 0; col < 64; col++) {
        if (tid < 64) {
            double v = (tid >= col) ? fabs(g_aug[tid * 128 + col]) : -1.0;
            int r = tid;
            for (int off = 16; off; off >>= 1) {
                double ov = __shfl_down_sync(0xffffffffu, v, off);
                int orr = __shfl_down_sync(0xffffffffu, r, off);
                if (ov > v) { v = ov; r = orr; }
            }
            if ((tid & 31) == 0) { s_bv[tid >> 5] = v; s_br[tid >> 5] = r; }
        }
        __syncthreads();
        if (tid == 0) s_piv = (s_bv[1] > s_bv[0]) ? s_br[1] : s_br[0];
        __syncthreads();
        int piv = s_piv;
        if (piv != col && tid < 128) {
            double t = g_aug[piv * 128 + tid];
            g_aug[piv * 128 + tid] = g_aug[col * 128 + tid];
            g_aug[col * 128 + tid] = t;
        }
        __syncthreads();
        if (tid == 0) s_pv = g_aug[col * 128 + col];
        __syncthreads();
        if (tid < 128) g_aug[col * 128 + tid] /= s_pv;
        __syncthreads();
        if (tid < 64) s_f[tid] = (tid == col) ? 0.0 : g_aug[tid * 128 + col];
        __syncthreads();
        for (int idx = tid; idx < 64 * 128; idx += 256) {
            int r = idx >> 7, c = idx & 127;
            g_aug[idx] -= s_f[r] * g_aug[col * 128 + c];
        }
        __syncthreads();
    }
    for (int idx = tid; idx < 4096; idx += 256)
        g_Finv[idx] = (float)g_aug[(idx >> 6) * 128 + 64 + (idx & 63)];
    // tail fold: Wf = proj_w^T @ obj_emb @ m_eff @ out_w^T
    if (tid == 0) {
        float m = functor_w[0];
        for (int i = 1; i < 64; i++) m = fmaxf(m, functor_w[i]);
        float s = 0.f;
        for (int i = 0; i < 64; i++) { float e = expf(functor_w[i] - m); s_fw[i] = e; s += e; }
        for (int i = 0; i < 64; i++) s_fw[i] /= s;
    }
    __syncthreads();
    for (int idx = tid; idx < 4096; idx += 256) {  // m_eff
        float s = 0.f;
        for (int m = 0; m < 64; m++) s += s_fw[m] * morphisms[m * 4096 + idx];
        s_a[idx] = s;
    }
    __syncthreads();
    for (int idx = tid; idx < 4096; idx += 256) {  // A2 = obj_emb @ m_eff
        int k = idx >> 6, j = idx & 63;
        float s = 0.f;
        for (int i = 0; i < 64; i++) s += obj_emb[k * 64 + i] * s_a[i * 64 + j];
        s_b[idx] = s;
    }
    __syncthreads();
    for (int idx = tid; idx < 4096; idx += 256) {  // A3 = A2 @ out_w^T
        int k = idx >> 6, o = idx & 63;
        float s = 0.f;
        for (int j = 0; j < 64; j++) s += s_b[k * 64 + j] * out_w[o * 64 + j];
        s_a[idx] = s;
    }
    __syncthreads();
    for (int idx = tid; idx < 4096; idx += 256) {  // Wf = proj_w^T @ A3
        int t = idx >> 6, o = idx & 63;
        float s = 0.f;
        for (int k = 0; k < 64; k++) s += proj_w[k * 64 + t] * s_a[k * 64 + o];
        g_Wf[idx] = s;
    }
    if (tid < 64) {
        float s = out_b[tid];
        for (int k = 0; k < 64; k++) s += proj_b[k] * s_a[k * 64 + tid];
        g_bf[tid] = s;
    }
}

// ============ K0b: Dsym[p][o] = sum_k (C[i,j,k]+C[j,i,k]) * Wf[k][o] ============
__global__ void k0b(const float* __restrict__ conn) {
    __shared__ float Wsh[4096];
    int tid = threadIdx.x;
    for (int idx = tid; idx < 4096; idx += 256) Wsh[idx] = g_Wf[idx];
    __syncthreads();
    int idx = blockIdx.x * 256 + tid;
    int p = idx >> 6, o = idx & 63;
    int i = g_pi[p], j = g_pj[p];
    const float* c1 = conn + (i * 64 + j) * 64;
    const float* c2 = conn + (j * 64 + i) * 64;
    float s = 0.f;
    if (i == j) { for (int k = 0; k < 64; k++) s += c1[k] * Wsh[k * 64 + o]; }
    else { for (int k = 0; k < 64; k++) s += (c1[k] + c2[k]) * Wsh[k * 64 + o]; }
    g_Dsym[idx] = s;
}

// ============ K1: topo[b,o] = sum_{j,d} (p[j,b,d,0]+p[j,b,d,1]) * K[o,j,d] ============
__global__ void __launch_bounds__(256, 1) k_topo(const float* __restrict__ pers,
                                                 const float* __restrict__ tk) {
    extern __shared__ float Ksh[];  // [768][64]
    int tid = threadIdx.x;
    for (int idx = tid; idx < 768 * 64; idx += 256) {
        int o = idx / 768, jd = idx % 768;
        Ksh[jd * 64 + o] = tk[idx];
    }
    __syncthreads();
    int b = blockIdx.x * 256 + tid;
    u64 acc[32];
#pragma unroll
    for (int q = 0; q < 32; q++) acc[q] = 0ull;
    for (int j = 0; j < 256; j++) {
        size_t base = ((size_t)j * Bn + b) * 6;
        float2 a0 = *(const float2*)(pers + base);
        float2 a1 = *(const float2*)(pers + base + 2);
        float2 a2 = *(const float2*)(pers + base + 4);
        float sd[3] = {a0.x + a0.y, a1.x + a1.y, a2.x + a2.y};
#pragma unroll
        for (int d = 0; d < 3; d++) {
            u64 sv = pk2(sd[d], sd[d]);
            const ulonglong2* row = (const ulonglong2*)(Ksh + (j * 3 + d) * 64);
#pragma unroll
            for (int q = 0; q < 16; q++) {
                ulonglong2 w = row[q];
                acc[2 * q] = ffma2(sv, w.x, acc[2 * q]);
                acc[2 * q + 1] = ffma2(sv, w.y, acc[2 * q + 1]);
            }
        }
    }
#pragma unroll
    for (int q = 0; q < 32; q++) {
        float lo, hi; upk2(acc[q], lo, hi);
        g_topo[(2 * q) * Bn + b] = lo;
        g_topo[(2 * q + 1) * Bn + b] = hi;
    }
}

// ============ K2: q/k/v ============
__global__ void __launch_bounds__(256, 1) k_qkv(const float* __restrict__ qb,
                                                const float* __restrict__ kb,
                                                const float* __restrict__ vb) {
    extern __shared__ float sm[];
    float* in_sh = sm;            // 16384
    float* W_sh = sm + 16384;     // 4096
    int tid = threadIdx.x, b0 = blockIdx.x * 256, b = b0 + tid;
    for (int idx = tid; idx < 16384; idx += 256)
        in_sh[idx] = g_topo[(idx >> 8) * Bn + b0 + (idx & 255)];
    const float* Wg[3] = {g_WqT, g_WkT, g_WvT};
    const float* bias[3] = {qb, kb, vb};
    float* outg[3] = {g_qv, g_kv, g_vv};
    for (int s = 0; s < 3; s++) {
        __syncthreads();
        for (int idx = tid; idx < 4096; idx += 256) W_sh[idx] = Wg[s][idx];
        __syncthreads();
        u64 acc[32];
#pragma unroll
        for (int q = 0; q < 32; q++) acc[q] = 0ull;
        gemv64(in_sh, W_sh, tid, acc);
#pragma unroll
        for (int q = 0; q < 32; q++) {
            float lo, hi; upk2(acc[q], lo, hi);
            outg[s][(2 * q) * Bn + b] = lo + bias[s][2 * q];
            outg[s][(2 * q + 1) * Bn + b] = hi + bias[s][2 * q + 1];
        }
    }
}

// ============ K3: attention (real softmax) + o-proj ============
__global__ void __launch_bounds__(256, 1) k_att(const float* __restrict__ ob) {
    extern __shared__ float sm[];
    float* k_sh = sm;                  // 16384
    float* v_sh = sm + 16384;          // 16384
    float* Wo_sh = sm + 32768;         // 4096
    float* cos_sh = sm + 36864;        // 64
    int tid = threadIdx.x, b0 = blockIdx.x * 256, b = b0 + tid;
    for (int idx = tid; idx < 16384; idx += 256) {
        int i = idx >> 8, t = idx & 255;
        k_sh[idx] = g_kv[i * Bn + b0 + t];
        v_sh[idx] = g_vv[i * Bn + b0 + t];
    }
    for (int idx = tid; idx < 4096; idx += 256) Wo_sh[idx] = g_WoT[idx];
    if (tid < 64) cos_sh[tid] = g_cosd[tid];
    __syncthreads();
    u64 acc[32];
#pragma unroll
    for (int q = 0; q < 32; q++) acc[q] = 0ull;
    for (int h = 0; h < 8; h++) {
        float qh[8];
#pragma unroll
        for (int d = 0; d < 8; d++) qh[d] = g_qv[(h * 8 + d) * Bn + b];
        float s[8];
#pragma unroll
        for (int g = 0; g < 8; g++) {
            float dot = 0.f;
#pragma unroll
            for (int d = 0; d < 8; d++) dot += qh[d] * k_sh[(g * 8 + d) * 256 + tid];
            s[g] = dot * cos_sh[h * 8 + g] * 0.35355339059327373f;
        }
        float m = s[0];
#pragma unroll
        for (int g = 1; g < 8; g++) m = fmaxf(m, s[g]);
        float sum = 0.f;
#pragma unroll
        for (int g = 0; g < 8; g++) { s[g] = expf(s[g] - m); sum += s[g]; }
        float inv = 1.0f / sum;
        float av[8] = {0, 0, 0, 0, 0, 0, 0, 0};
#pragma unroll
        for (int g = 0; g < 8; g++) {
            float w = s[g] * inv;
#pragma unroll
            for (int d = 0; d < 8; d++) av[d] += w * v_sh[(g * 8 + d) * 256 + tid];
        }
#pragma unroll
        for (int d = 0; d < 8; d++) {
            u64 xv = pk2(av[d], av[d]);
            const ulonglong2* row = (const ulonglong2*)(Wo_sh + (h * 8 + d) * 64);
#pragma unroll
            for (int q = 0; q < 16; q++) {
                ulonglong2 w = row[q];
                acc[2 * q] = ffma2(xv, w.x, acc[2 * q]);
                acc[2 * q + 1] = ffma2(xv, w.y, acc[2 * q + 1]);
            }
        }
    }
#pragma unroll
    for (int q = 0; q < 32; q++) {
        float lo, hi; upk2(acc[q], lo, hi);
        g_quant[(2 * q) * Bn + b] = lo + ob[2 * q];
        g_quant[(2 * q + 1) * Bn + b] = hi + ob[2 * q + 1];
    }
}

// ============ K4: update + candidate gates ============
__global__ void __launch_bounds__(256, 1) k_uc(const float* __restrict__ ub,
                                               const float* __restrict__ sb) {
    extern __shared__ float sm[];
    float* in_sh = sm;
    float* W_sh = sm + 16384;
    int tid = threadIdx.x, b0 = blockIdx.x * 256, b = b0 + tid;
    for (int idx = tid; idx < 16384; idx += 256)
        in_sh[idx] = g_quant[(idx >> 8) * Bn + b0 + (idx & 255)];
    __syncthreads();
    for (int idx = tid; idx < 4096; idx += 256) W_sh[idx] = g_WuT[idx];
    __syncthreads();
    {
        u64 acc[32];
#pragma unroll
        for (int q = 0; q < 32; q++) acc[q] = 0ull;
        gemv64(in_sh, W_sh, tid, acc);
#pragma unroll
        for (int q = 0; q < 32; q++) {
            float lo, hi; upk2(acc[q], lo, hi);
            g_uv[(2 * q) * Bn + b] = 1.0f / (1.0f + expf(-(lo + ub[2 * q])));
            g_uv[(2 * q + 1) * Bn + b] = 1.0f / (1.0f + expf(-(hi + ub[2 * q + 1])));
        }
    }
    __syncthreads();
    for (int idx = tid; idx < 4096; idx += 256) W_sh[idx] = g_WsT[idx];
    __syncthreads();
    {
        u64 acc[32];
#pragma unroll
        for (int q = 0; q < 32; q++) acc[q] = 0ull;
        gemv64(in_sh, W_sh, tid, acc);
#pragma unroll
        for (int q = 0; q < 32; q++) {
            float lo, hi; upk2(acc[q], lo, hi);
            g_cand[(2 * q) * Bn + b] = tanhf(lo + sb[2 * q]);
            g_cand[(2 * q + 1) * Bn + b] = tanhf(hi + sb[2 * q + 1]);
        }
    }
}

// ============ K5: ng = Finv@cand; h = u*ng; xm = h@metric ============
__global__ void __launch_bounds__(256, 1) k_nx() {
    extern __shared__ float sm[];
    float* in_sh = sm;              // 16384
    float* F_sh = sm + 16384;       // 4096
    float* M_sh = sm + 20480;       // 4096
    int tid = threadIdx.x, b0 = blockIdx.x * 256, b = b0 + tid;
    for (int idx = tid; idx < 16384; idx += 256)
        in_sh[idx] = g_cand[(idx >> 8) * Bn + b0 + (idx & 255)];
    for (int idx = tid; idx < 4096; idx += 256) {
        F_sh[idx] = g_Finv[idx];
        M_sh[idx] = g_metric[idx];
    }
    __syncthreads();
    u64 acc[32];
#pragma unroll
    for (int q = 0; q < 32; q++) acc[q] = 0ull;
    gemv64(in_sh, F_sh, tid, acc);  // Finv symmetric
    __syncthreads();
#pragma unroll
    for (int q = 0; q < 32; q++) {
        float lo, hi; upk2(acc[q], lo, hi);
        in_sh[(2 * q) * 256 + tid] = lo * g_uv[(2 * q) * Bn + b];
        in_sh[(2 * q + 1) * 256 + tid] = hi * g_uv[(2 * q + 1) * Bn + b];
    }
    __syncthreads();
#pragma unroll
    for (int q = 0; q < 32; q++) acc[q] = 0ull;
    gemv64(in_sh, M_sh, tid, acc);  // metric symmetric
#pragma unroll
    for (int q = 0; q < 32; q++) {
        float lo, hi; upk2(acc[q], lo, hi);
        g_xm[(2 * q) * Bn + b] = lo;
        g_xm[(2 * q + 1) * Bn + b] = hi;
    }
}

// ============ K6: out = bf + xm@Wf + sum_p (xm_i*xm_j)*Dsym[p,:] ============
__global__ void __launch_bounds__(256, 1) k_bil(float* __restrict__ out) {
    extern __shared__ float sm[];
    float* xm_sh = sm;                 // 16384
    float* Wf_sh = sm + 16384;         // 4096
    float* Dch = sm + 20480;           // 4096 (64 pairs x 64)
    float* bf_sh = sm + 24576;         // 64
    unsigned char* pi_sh = (unsigned char*)(sm + 24640);
    unsigned char* pj_sh = pi_sh + NP;
    int tid = threadIdx.x, b0 = blockIdx.x * 256, b = b0 + tid;
    for (int idx = tid; idx < 16384; idx += 256)
        xm_sh[idx] = g_xm[(idx >> 8) * Bn + b0 + (idx & 255)];
    for (int idx = tid; idx < 4096; idx += 256) Wf_sh[idx] = g_Wf[idx];
    if (tid < 64) bf_sh[tid] = g_bf[tid];
    for (int p = tid; p < NP; p += 256) { pi_sh[p] = g_pi[p]; pj_sh[p] = g_pj[p]; }
    __syncthreads();
    u64 acc[32];
#pragma unroll
    for (int q = 0; q < 32; q++) acc[q] = 0ull;
    gemv64(xm_sh, Wf_sh, tid, acc);   // linear part
    for (int c0 = 0; c0 < NP; c0 += 64) {
        int nch = min(64, NP - c0);
        __syncthreads();
        for (int idx = tid; idx < nch * 64; idx += 256) Dch[idx] = g_Dsym[c0 * 64 + idx];
        __syncthreads();
        for (int p = 0; p < nch; p++) {
            int i = pi_sh[c0 + p], j = pj_sh[c0 + p];
            float prod = xm_sh[i * 256 + tid] * xm_sh[j * 256 + tid];
            u64 pv = pk2(prod, prod);
            const ulonglong2* row = (const ulonglong2*)(Dch + p * 64);
#pragma unroll
            for (int q = 0; q < 16; q++) {
                ulonglong2 w = row[q];
                acc[2 * q] = ffma2(pv, w.x, acc[2 * q]);
                acc[2 * q + 1] = ffma2(pv, w.y, acc[2 * q + 1]);
            }
        }
    }
    float4* orow = (float4*)(out + (size_t)b * 64);
#pragma unroll
    for (int q = 0; q < 16; q++) {
        float a0, a1, a2, a3;
        upk2(acc[2 * q], a0, a1);
        upk2(acc[2 * q + 1], a2, a3);
        orow[q] = make_float4(a0 + bf_sh[4 * q], a1 + bf_sh[4 * q + 1],
                              a2 + bf_sh[4 * q + 2], a3 + bf_sh[4 * q + 3]);
    }
}

extern "C" void kernel_launch(void* const* d_in, const int* in_sizes, int n_in,
                              void* d_out, int out_size) {
    const float* pers     = (const float*)d_in[1];
    const float* tk       = (const float*)d_in[2];
    const float* q_w = (const float*)d_in[3],  *q_b = (const float*)d_in[4];
    const float* k_w = (const float*)d_in[5],  *k_b = (const float*)d_in[6];
    const float* v_w = (const float*)d_in[7],  *v_b = (const float*)d_in[8];
    const float* o_w = (const float*)d_in[9],  *o_b = (const float*)d_in[10];
    const float* phase = (const float*)d_in[11];
    const float* update_w = (const float*)d_in[12], *update_b = (const float*)d_in[13];
    const float* state_w  = (const float*)d_in[16], *state_b  = (const float*)d_in[17];
    const float* fisher_m = (const float*)d_in[18];
    const float* metric_m = (const float*)d_in[19];
    const float* connection = (const float*)d_in[20];
    const float* proj_w = (const float*)d_in[21], *proj_b = (const float*)d_in[22];
    const float* obj_emb = (const float*)d_in[23];
    const float* morphisms = (const float*)d_in[24];
    const float* functor_w = (const float*)d_in[25];
    const float* out_w = (const float*)d_in[26], *out_b = (const float*)d_in[27];
    float* out = (float*)d_out;

    static bool attr_set = false;
    if (!attr_set) {
        cudaFuncSetAttribute(k_topo, cudaFuncAttributeMaxDynamicSharedMemorySize, 768 * 64 * 4);
        cudaFuncSetAttribute(k_qkv, cudaFuncAttributeMaxDynamicSharedMemorySize, 20480 * 4);
        cudaFuncSetAttribute(k_att, cudaFuncAttributeMaxDynamicSharedMemorySize, 36928 * 4);
        cudaFuncSetAttribute(k_uc, cudaFuncAttributeMaxDynamicSharedMemorySize, 20480 * 4);
        cudaFuncSetAttribute(k_nx, cudaFuncAttributeMaxDynamicSharedMemorySize, 24576 * 4);
        cudaFuncSetAttribute(k_bil, cudaFuncAttributeMaxDynamicSharedMemorySize, 24640 * 4 + 2 * NP);
        attr_set = true;
    }
    int grid = Bn / 256;
    k0a<<<1, 256>>>(phase, q_w, k_w, v_w, o_w, update_w, state_w, fisher_m, metric_m,
                    proj_w, proj_b, obj_emb, morphisms, functor_w, out_w, out_b);
    k0b<<<NP * 64 / 256, 256>>>(connection);
    k_topo<<<grid, 256, 768 * 64 * 4>>>(pers, tk);
    k_qkv<<<grid, 256, 20480 * 4>>>(q_b, k_b, v_b);
    k_att<<<grid, 256, 36928 * 4>>>(o_b);
    k_uc<<<grid, 256, 20480 * 4>>>(update_b, state_b);
    k_nx<<<grid, 256, 24576 * 4>>>();
    k_bil<<<grid, 256, 24640 * 4 + 2 * NP>>>(out);
}